// round 14
// baseline (speedup 1.0000x reference)
#include <cuda_runtime.h>
#include <cuda_fp16.h>
#include <cstdint>

// ---------------------------------------------------------------------------
// ResidualGNNLayer (sm_103, fp16 mma.sync):
//   k_gemm1: B(W1 tile)-resident in smem (full 64KB fill, FIXED), 4 row-tiles
//            per CTA -> far fewer LDGSTS per stage.  grid (98, 4).
//   k_gemm2: unchanged (128 thr, 3 CTAs/SM).
// ---------------------------------------------------------------------------

#define DD 128
#define HH 512
#define KP 256
#define CAP 128
#define NN_MAX 50176    // 98 * 4 * 128 (padded; rows >= Nn stay zero)

static __device__ int   g_is64;
static __device__ int   g_cnt[NN_MAX];
static __device__ float g_dist[NN_MAX];
static __device__ int   g_slots[(size_t)NN_MAX * CAP];

static __device__ __half g_xh[(size_t)NN_MAX * DD];
static __device__ __half g_feat[(size_t)NN_MAX * KP];
static __device__ __half g_h[(size_t)NN_MAX * HH];
static __device__ __half g_w1t[HH * KP];              // [n=512][k=256]
static __device__ __half g_w2t[DD * HH];              // [n=128][k=512]

// ---------------- PTX helpers ----------------------------------------------
__device__ __forceinline__ uint32_t smem_u32(const void* p) {
    uint32_t a;
    asm("{ .reg .u64 t; cvta.to.shared.u64 t, %1; cvt.u32.u64 %0, t; }"
        : "=r"(a) : "l"(p));
    return a;
}
__device__ __forceinline__ void cp16(uint32_t d, const void* s) {
    asm volatile("cp.async.ca.shared.global [%0], [%1], 16;" :: "r"(d), "l"(s));
}
#define CP_COMMIT() asm volatile("cp.async.commit_group;" ::: "memory")
#define CP_WAIT(n)  asm volatile("cp.async.wait_group %0;" :: "n"(n) : "memory")

__device__ __forceinline__ void ldm_x4(uint32_t addr, uint32_t r[4]) {
    asm volatile("ldmatrix.sync.aligned.m8n8.x4.shared.b16 {%0,%1,%2,%3}, [%4];"
                 : "=r"(r[0]), "=r"(r[1]), "=r"(r[2]), "=r"(r[3]) : "r"(addr));
}
__device__ __forceinline__ void mma16816(float d[4], const uint32_t a[4],
                                         const uint32_t b0, const uint32_t b1) {
    asm volatile(
        "mma.sync.aligned.m16n8k16.row.col.f32.f16.f16.f32 "
        "{%0,%1,%2,%3},{%4,%5,%6,%7},{%8,%9},{%0,%1,%2,%3};"
        : "+f"(d[0]), "+f"(d[1]), "+f"(d[2]), "+f"(d[3])
        : "r"(a[0]), "r"(a[1]), "r"(a[2]), "r"(a[3]), "r"(b0), "r"(b1));
}
__device__ __forceinline__ uint32_t swz(int r, int c) {
    return (uint32_t)(r * 64 + (((((c >> 4) ^ (r >> 1)) & 3) << 4) | (c & 15)));
}

// ---------------- prep ------------------------------------------------------
__global__ void k_prep(const float* __restrict__ W1, const float* __restrict__ W2,
                       const float* __restrict__ x,
                       const void* __restrict__ eraw, int E, int Nn) {
    int b = blockIdx.x, t = threadIdx.x;
    if (b == 0) {
        if (t == 0) {
            const long long* p64 = (const long long*)eraw;
            int ok64 = 1;
            int step = E / 32; if (step < 1) step = 1;
            for (int i = 0; i < 32; i++) {
                long long idx = (long long)i * step;
                if (idx >= E) break;
                long long v = p64[idx];
                if (v < 0 || v >= Nn) { ok64 = 0; break; }
            }
            g_is64 = ok64;
        }
        return;
    }
    int ZB = (Nn + 255) / 256;
    if (b - 1 < ZB) {
        int i = (b - 1) * 256 + t;
        if (i < Nn) { g_cnt[i] = 0; g_dist[i] = 0.f; }
        return;
    }
    int b2 = b - 1 - ZB;
    if (b2 < (HH * KP) / 256) {
        int idx = b2 * 256 + t;
        int n = idx >> 8, k = idx & 255;
        g_w1t[idx] = __float2half_rn(W1[k * HH + n]);
        return;
    }
    int b3 = b2 - (HH * KP) / 256;
    if (b3 < (DD * HH) / 256) {
        int idx = b3 * 256 + t;
        int n = idx >> 9, k = idx & 511;
        g_w2t[idx] = __float2half_rn(W2[k * DD + n]);
        return;
    }
    int b4 = b3 - (DD * HH) / 256;
    int idx = b4 * 256 + t;
    if (idx < Nn * DD) g_xh[idx] = __float2half_rn(x[idx]);
}

__global__ void k_edge(const void* __restrict__ eraw,
                       const float* __restrict__ ed, int E, int Nn) {
    int e = blockIdx.x * blockDim.x + threadIdx.x;
    if (e >= E) return;
    int src, dst;
    if (g_is64) {
        const long long* p = (const long long*)eraw;
        src = (int)p[e]; dst = (int)p[E + e];
    } else {
        const int* p = (const int*)eraw;
        src = p[e]; dst = p[E + e];
    }
    src = min(max(src, 0), Nn - 1);
    dst = min(max(dst, 0), Nn - 1);
    int p = atomicAdd(&g_cnt[src], 1);
    if (p < CAP) g_slots[(size_t)src * CAP + p] = dst;
    atomicAdd(&g_dist[src], ed[e]);
}

// 2 nodes per warp: 16 lanes x uint4 (16B) per row
__global__ void k_feat(const float* __restrict__ degrees, int Nn) {
    int warp = (blockIdx.x * blockDim.x + threadIdx.x) >> 5;
    int lane = threadIdx.x & 31;
    int sub = lane >> 4, sl = lane & 15;
    int gw = warp * 2 + sub;
    if (gw >= Nn) return;
    int cnt = g_cnt[gw]; if (cnt > CAP) cnt = CAP;
    const int* slots = g_slots + (size_t)gw * CAP;
    float acc[8];
#pragma unroll
    for (int i = 0; i < 8; i++) acc[i] = 0.f;
    int dnext = (cnt > 0) ? slots[0] : 0;
    for (int j = 0; j < cnt; j++) {
        int dcur = dnext;
        if (j + 1 < cnt) dnext = slots[j + 1];
        uint4 u = *(const uint4*)(g_xh + (size_t)dcur * DD + sl * 8);
        float2 f0 = __half22float2(*(__half2*)&u.x);
        float2 f1 = __half22float2(*(__half2*)&u.y);
        float2 f2 = __half22float2(*(__half2*)&u.z);
        float2 f3 = __half22float2(*(__half2*)&u.w);
        acc[0] += f0.x; acc[1] += f0.y; acc[2] += f1.x; acc[3] += f1.y;
        acc[4] += f2.x; acc[5] += f2.y; acc[6] += f3.x; acc[7] += f3.y;
    }
    float inv = 1.f / fmaxf(degrees[gw], 1.f);
    __half* f = g_feat + (size_t)gw * KP;
    *(uint4*)(f + sl * 8) = *(const uint4*)(g_xh + (size_t)gw * DD + sl * 8);
    uint4 o;
    *(__half2*)&o.x = __floats2half2_rn(acc[0] * inv, acc[1] * inv);
    *(__half2*)&o.y = __floats2half2_rn(acc[2] * inv, acc[3] * inv);
    *(__half2*)&o.z = __floats2half2_rn(acc[4] * inv, acc[5] * inv);
    *(__half2*)&o.w = __floats2half2_rn(acc[6] * inv, acc[7] * inv);
    *(uint4*)(f + DD + sl * 8) = o;
}

// ---------------------------------------------------------------------------
// GEMM fragments: 4 warps (2x2), warp tile 64x64
// ---------------------------------------------------------------------------
struct Frag64 {
    uint32_t Ah[4][4];
    uint32_t Bh[8][2];
};
__device__ __forceinline__ void load_f(uint32_t abase, uint32_t bbase,
                                       Frag64& f) {
#pragma unroll
    for (int mf = 0; mf < 4; mf++)
        ldm_x4(abase + mf * 1024, f.Ah[mf]);
#pragma unroll
    for (int p = 0; p < 4; p++) {
        uint32_t r[4];
        ldm_x4(bbase + p * 1024, r);
        f.Bh[p * 2 + 0][0] = r[0]; f.Bh[p * 2 + 0][1] = r[2];
        f.Bh[p * 2 + 1][0] = r[1]; f.Bh[p * 2 + 1][1] = r[3];
    }
}
__device__ __forceinline__ void mma_all64(float acc[4][8][4], const Frag64& f) {
#pragma unroll
    for (int mf = 0; mf < 4; mf++)
#pragma unroll
        for (int nf = 0; nf < 8; nf++)
            mma16816(acc[mf][nf], f.Ah[mf], f.Bh[nf][0], f.Bh[nf][1]);
}

// ---------------------------------------------------------------------------
// GEMM1 v2: B resident (64KB, FULL fill), A streamed; 4 row-tiles per CTA
// smem: B @0 (8 chunks x [128r][64B]); A stages @65536 (3 x 8KB);
//       degv @90112, mdv @90624.  Total 91136 -> 2 CTAs/SM.
// ---------------------------------------------------------------------------
#define G1_B     0
#define G1_A     65536
#define G1_DEG   90112
#define G1_MD    90624
#define G1_SMEM  91136
#define TILES_PER_CTA 4

__global__ __launch_bounds__(128, 2) void k_gemm1(
    const float* __restrict__ W1, const float* __restrict__ b1,
    const float* __restrict__ degrees, int Nn, int n_tiles) {
    extern __shared__ __align__(128) char sm[];
    uint32_t base = smem_u32(sm);
    int t = threadIdx.x, lane = t & 31, wid = t >> 5;
    int wm = wid >> 1, wn = wid & 1;
    int tile0 = blockIdx.x * TILES_PER_CTA;
    int col0 = blockIdx.y * 128;
    int ntl = n_tiles - tile0;
    if (ntl > TILES_PER_CTA) ntl = TILES_PER_CTA;

    float* degv = (float*)(sm + G1_DEG);
    float* mdv  = (float*)(sm + G1_MD);

    int lr = t >> 2, seg = (t & 3) * 16;
    uint32_t dsw = swz(lr, seg);                    // rows 0..31 swizzled
    const char* pB = (const char*)(g_w1t + (size_t)(col0 + lr) * KP) + seg;

    // ---- B fill: FULL 64KB tile (4 row-groups x 8 k-chunks = 32 cp16/thr) ----
#pragma unroll
    for (int i = 0; i < 4; i++)
#pragma unroll
        for (int c = 0; c < 8; c++)
            cp16(base + G1_B + c * 8192 + dsw + 2048 * i,
                 pB + (size_t)i * 32 * (KP * 2) + c * 64);
    CP_COMMIT();

    uint32_t aoff = swz(wm * 64 + (lane & 15), (lane >> 4) * 16);
    uint32_t boff = swz(wn * 64 + (lane & 15), (lane >> 4) * 16);

    const int NS = ntl * 8;
    const char* pA0 = (const char*)g_feat + seg;

    // prologue A stages 0,1
#pragma unroll 1
    for (int ss = 0; ss < 2; ss++) {
        int rt = ss >> 3, s = ss & 7;
        const char* pA = pA0 + ((size_t)(tile0 + rt) * 128 + lr) * (KP * 2);
#pragma unroll
        for (int i = 0; i < 4; i++)
            cp16(base + G1_A + (ss % 3) * 8192 + dsw + 2048 * i,
                 pA + (size_t)i * 32 * (KP * 2) + s * 64);
        CP_COMMIT();
    }

    float acc[4][8][4];
#pragma unroll
    for (int a = 0; a < 4; a++)
#pragma unroll
        for (int b = 0; b < 8; b++)
#pragma unroll
            for (int c = 0; c < 4; c++) acc[a][b][c] = 0.f;

#pragma unroll 1
    for (int ss = 0; ss < NS; ss++) {
        int rt = ss >> 3, s = ss & 7;
        if (ss < NS - 1) { CP_WAIT(1); } else { CP_WAIT(0); }
        __syncthreads();
        if (s == 0) {                      // stage this tile's per-row scalars
            int gr = (tile0 + rt) * 128 + t;
            float dr = (gr < Nn) ? degrees[gr] : 0.f;
            float ds = (gr < Nn) ? g_dist[gr] : 0.f;
            degv[t] = dr;
            mdv[t]  = ds / fmaxf(dr, 1.f);
        }
        if (ss + 2 < NS) {
            int ss2 = ss + 2, rt2 = ss2 >> 3, s2 = ss2 & 7;
            const char* pA = pA0 + ((size_t)(tile0 + rt2) * 128 + lr) * (KP * 2);
#pragma unroll
            for (int i = 0; i < 4; i++)
                cp16(base + G1_A + (ss2 % 3) * 8192 + dsw + 2048 * i,
                     pA + (size_t)i * 32 * (KP * 2) + s2 * 64);
            CP_COMMIT();
        }
        uint32_t ab = base + G1_A + (ss % 3) * 8192 + aoff;
        uint32_t bb = base + G1_B + s * 8192 + boff;
#pragma unroll
        for (int ks = 0; ks < 2; ks++) {
            Frag64 f;
            load_f(ab ^ (ks * 32u), bb ^ (ks * 32u), f);
            mma_all64(acc, f);
        }

        if (s == 7) {
            // ---- epilogue for row tile rt ----
            int row0 = (tile0 + rt) * 128;
#pragma unroll
            for (int nf = 0; nf < 8; nf++) {
                int cg = col0 + wn * 64 + nf * 8 + (lane & 3) * 2;
                float b10 = __ldg(b1 + cg), b11 = __ldg(b1 + cg + 1);
                float wd0 = __ldg(W1 + 256 * HH + cg), wd1 = __ldg(W1 + 256 * HH + cg + 1);
                float wq0 = __ldg(W1 + 257 * HH + cg), wq1 = __ldg(W1 + 257 * HH + cg + 1);
#pragma unroll
                for (int mf = 0; mf < 4; mf++) {
                    int rl = wm * 64 + mf * 16 + (lane >> 2);
                    float d0 = degv[rl], m0 = mdv[rl];
                    float d1 = degv[rl + 8], m1 = mdv[rl + 8];
                    float v00 = fmaxf(acc[mf][nf][0] + b10 + d0 * wd0 + m0 * wq0, 0.f);
                    float v01 = fmaxf(acc[mf][nf][1] + b11 + d0 * wd1 + m0 * wq1, 0.f);
                    float v10 = fmaxf(acc[mf][nf][2] + b10 + d1 * wd0 + m1 * wq0, 0.f);
                    float v11 = fmaxf(acc[mf][nf][3] + b11 + d1 * wd1 + m1 * wq1, 0.f);
                    *(__half2*)(g_h + (size_t)(row0 + rl) * HH + cg) =
                        __floats2half2_rn(v00, v01);
                    *(__half2*)(g_h + (size_t)(row0 + rl + 8) * HH + cg) =
                        __floats2half2_rn(v10, v11);
                    acc[mf][nf][0] = 0.f; acc[mf][nf][1] = 0.f;
                    acc[mf][nf][2] = 0.f; acc[mf][nf][3] = 0.f;
                }
            }
        }
    }
}

// ---------------------------------------------------------------------------
// GEMM2 + residual + LN: out = LN(x + h@W2 + b2); K=512, 16 steps (unchanged)
// ---------------------------------------------------------------------------
#define STG(s) ((s) * 16384)
#define G2_SMEM 52224
__global__ __launch_bounds__(128, 3) void k_gemm2(
    const float* __restrict__ x, const float* __restrict__ b2,
    const float* __restrict__ gamma, const float* __restrict__ beta,
    float* __restrict__ out, int Nn) {
    extern __shared__ __align__(128) char sm[];
    uint32_t base = smem_u32(sm);
    int t = threadIdx.x, lane = t & 31, wid = t >> 5;
    int wm = wid >> 1, wn = wid & 1;
    int row0 = blockIdx.x * 128;
    float* part0 = (float*)(sm + 49152);
    float* part1 = (float*)(sm + 50176);
    float* mus   = (float*)(sm + 51200);
    float* rss   = (float*)(sm + 51712);

    float acc[4][8][4];
#pragma unroll
    for (int a = 0; a < 4; a++)
#pragma unroll
        for (int b = 0; b < 8; b++)
#pragma unroll
            for (int c = 0; c < 4; c++) acc[a][b][c] = 0.f;

    uint32_t aoff = swz(wm * 64 + (lane & 15), (lane >> 4) * 16);
    uint32_t boff = 8192 + swz(wn * 64 + (lane & 15), (lane >> 4) * 16);

    int lr = t >> 2, seg = (t & 3) * 16;
    const char* pA = (const char*)(g_h + (size_t)(row0 + lr) * HH) + seg;
    const char* pB = (const char*)(g_w2t + (size_t)lr * HH) + seg;
    uint32_t dA = base + swz(lr, seg);
    const int RB = HH * 2 * 32;

#pragma unroll 1
    for (int s = 0; s < 2; s++) {
#pragma unroll
        for (int i = 0; i < 4; i++) {
            cp16(dA + STG(s) + 2048 * i, pA + i * RB + s * 64);
            cp16(dA + STG(s) + 8192 + 2048 * i, pB + i * RB + s * 64);
        }
        CP_COMMIT();
    }
#pragma unroll 1
    for (int s = 0; s < 16; s++) {
        if (s < 15) { CP_WAIT(1); } else { CP_WAIT(0); }
        __syncthreads();
        if (s + 2 < 16) {
            int sp = (s + 2) % 3;
#pragma unroll
            for (int i = 0; i < 4; i++) {
                cp16(dA + STG(sp) + 2048 * i, pA + i * RB + (s + 2) * 64);
                cp16(dA + STG(sp) + 8192 + 2048 * i, pB + i * RB + (s + 2) * 64);
            }
            CP_COMMIT();
        }
        uint32_t sb = base + STG(s % 3);
#pragma unroll
        for (int ks = 0; ks < 2; ks++) {
            Frag64 f;
            load_f(sb + (aoff ^ (ks * 32u)), sb + (boff ^ (ks * 32u)), f);
            mma_all64(acc, f);
        }
    }

#pragma unroll
    for (int nf = 0; nf < 8; nf++) {
        int cc = wn * 64 + nf * 8 + (lane & 3) * 2;
        float b20 = __ldg(b2 + cc), b21 = __ldg(b2 + cc + 1);
#pragma unroll
        for (int mf = 0; mf < 4; mf++) {
            int g0 = row0 + wm * 64 + mf * 16 + (lane >> 2);
            float2 xv0 = make_float2(0.f, 0.f), xv1 = xv0;
            if (g0 < Nn)     xv0 = *(const float2*)(x + (size_t)g0 * DD + cc);
            if (g0 + 8 < Nn) xv1 = *(const float2*)(x + (size_t)(g0 + 8) * DD + cc);
            acc[mf][nf][0] += b20 + xv0.x;
            acc[mf][nf][1] += b21 + xv0.y;
            acc[mf][nf][2] += b20 + xv1.x;
            acc[mf][nf][3] += b21 + xv1.y;
        }
    }
#pragma unroll
    for (int mf = 0; mf < 4; mf++) {
#pragma unroll
        for (int h = 0; h < 2; h++) {
            float s0 = 0.f, s1 = 0.f;
#pragma unroll
            for (int nf = 0; nf < 8; nf++) {
                float a0 = acc[mf][nf][2 * h], a1 = acc[mf][nf][2 * h + 1];
                s0 += a0 + a1;
                s1 += a0 * a0 + a1 * a1;
            }
            s0 += __shfl_xor_sync(0xffffffffu, s0, 1);
            s1 += __shfl_xor_sync(0xffffffffu, s1, 1);
            s0 += __shfl_xor_sync(0xffffffffu, s0, 2);
            s1 += __shfl_xor_sync(0xffffffffu, s1, 2);
            if ((lane & 3) == 0) {
                int rl = wm * 64 + mf * 16 + (lane >> 2) + h * 8;
                part0[wn * 128 + rl] = s0;
                part1[wn * 128 + rl] = s1;
            }
        }
    }
    __syncthreads();
    {
        float s0 = part0[t] + part0[128 + t];
        float s1 = part1[t] + part1[128 + t];
        float mu = s0 * (1.f / 128.f);
        float var = s1 * (1.f / 128.f) - mu * mu;
        mus[t] = mu;
        rss[t] = rsqrtf(var + 1e-5f);
    }
    __syncthreads();
#pragma unroll
    for (int nf = 0; nf < 8; nf++) {
        int cc = wn * 64 + nf * 8 + (lane & 3) * 2;
        float gg0 = __ldg(gamma + cc), gg1 = __ldg(gamma + cc + 1);
        float be0 = __ldg(beta + cc), be1 = __ldg(beta + cc + 1);
#pragma unroll
        for (int mf = 0; mf < 4; mf++) {
            int rl = wm * 64 + mf * 16 + (lane >> 2);
            int g0 = row0 + rl;
            if (g0 < Nn) {
                float mu = mus[rl], rs = rss[rl];
                float2 o;
                o.x = (acc[mf][nf][0] - mu) * rs * gg0 + be0;
                o.y = (acc[mf][nf][1] - mu) * rs * gg1 + be1;
                *(float2*)(out + (size_t)g0 * DD + cc) = o;
            }
            if (g0 + 8 < Nn) {
                float mu = mus[rl + 8], rs = rss[rl + 8];
                float2 o;
                o.x = (acc[mf][nf][2] - mu) * rs * gg0 + be0;
                o.y = (acc[mf][nf][3] - mu) * rs * gg1 + be1;
                *(float2*)(out + (size_t)(g0 + 8) * DD + cc) = o;
            }
        }
    }
}

// ---------------------------------------------------------------------------
extern "C" void kernel_launch(void* const* d_in, const int* in_sizes, int n_in,
                              void* d_out, int out_size) {
    const float* x       = (const float*)d_in[0];
    const float* W1      = (const float*)d_in[1];
    const float* b1      = (const float*)d_in[2];
    const float* W2      = (const float*)d_in[3];
    const float* b2      = (const float*)d_in[4];
    const float* gamma   = (const float*)d_in[5];
    const float* beta    = (const float*)d_in[6];
    const void*  ei      = d_in[7];
    const float* ed      = (const float*)d_in[8];
    const float* degrees = (const float*)d_in[9];

    int Nn = in_sizes[0] / DD;
    int E  = in_sizes[8];

    cudaFuncSetAttribute(k_gemm1, cudaFuncAttributeMaxDynamicSharedMemorySize, G1_SMEM);
    cudaFuncSetAttribute(k_gemm2, cudaFuncAttributeMaxDynamicSharedMemorySize, G2_SMEM);

    int ZB = (Nn + 255) / 256;
    int XB = (Nn * DD + 255) / 256;
    int prep_blocks = 1 + ZB + (HH * KP) / 256 + (DD * HH) / 256 + XB;
    k_prep<<<prep_blocks, 256>>>(W1, W2, x, ei, E, Nn);
    k_edge<<<(E + 255) / 256, 256>>>(ei, ed, E, Nn);
    k_feat<<<(Nn + 15) / 16, 256>>>(degrees, Nn);

    int mt = (Nn + 127) / 128;                       // 391 row tiles
    int mg = (mt + TILES_PER_CTA - 1) / TILES_PER_CTA;  // 98 groups
    k_gemm1<<<dim3(mg, 4), 128, G1_SMEM>>>(W1, b1, degrees, Nn, mt);
    k_gemm2<<<mt, 128, G2_SMEM>>>(x, b2, gamma, beta, (float*)d_out, Nn);
}

// round 15
// speedup vs baseline: 1.0851x; 1.0851x over previous
#include <cuda_runtime.h>
#include <cuda_fp16.h>
#include <cstdint>

// ---------------------------------------------------------------------------
// ResidualGNNLayer (sm_103, fp16 mma.sync, R12 GEMM config):
//   k_prep: detect + zero + W1/W2 fp16 transpose + x->fp16
//   k_edge: bucket edges; k_feat: 2 nodes/warp gather-mean -> agg only
//   k_gemm1: h = relu([xh|agg]@W1 + b1 + rank2(deg,md)); A dual-source loader
//   k_gemm2: out = LN(x + h@W2 + b2)
//   GEMMs: 128 thr / 4 warps (2x2) of 64x64, BK=32, 3-stage, (128,3) bounds.
// ---------------------------------------------------------------------------

#define DD 128
#define HH 512
#define KP 256
#define CAP 128
#define NN_MAX 50048    // 391 * 128

static __device__ int   g_is64;
static __device__ int   g_cnt[NN_MAX];
static __device__ float g_dist[NN_MAX];
static __device__ int   g_slots[(size_t)NN_MAX * CAP];

static __device__ __half g_xh[(size_t)NN_MAX * DD];
static __device__ __half g_agg[(size_t)NN_MAX * DD];
static __device__ __half g_h[(size_t)NN_MAX * HH];
static __device__ __half g_w1t[HH * KP];              // [n=512][k=256]
static __device__ __half g_w2t[DD * HH];              // [n=128][k=512]

// ---------------- PTX helpers ----------------------------------------------
__device__ __forceinline__ uint32_t smem_u32(const void* p) {
    uint32_t a;
    asm("{ .reg .u64 t; cvta.to.shared.u64 t, %1; cvt.u32.u64 %0, t; }"
        : "=r"(a) : "l"(p));
    return a;
}
__device__ __forceinline__ void cp16(uint32_t d, const void* s) {
    asm volatile("cp.async.ca.shared.global [%0], [%1], 16;" :: "r"(d), "l"(s));
}
#define CP_COMMIT() asm volatile("cp.async.commit_group;" ::: "memory")
#define CP_WAIT(n)  asm volatile("cp.async.wait_group %0;" :: "n"(n) : "memory")

__device__ __forceinline__ void ldm_x4(uint32_t addr, uint32_t r[4]) {
    asm volatile("ldmatrix.sync.aligned.m8n8.x4.shared.b16 {%0,%1,%2,%3}, [%4];"
                 : "=r"(r[0]), "=r"(r[1]), "=r"(r[2]), "=r"(r[3]) : "r"(addr));
}
__device__ __forceinline__ void mma16816(float d[4], const uint32_t a[4],
                                         const uint32_t b0, const uint32_t b1) {
    asm volatile(
        "mma.sync.aligned.m16n8k16.row.col.f32.f16.f16.f32 "
        "{%0,%1,%2,%3},{%4,%5,%6,%7},{%8,%9},{%0,%1,%2,%3};"
        : "+f"(d[0]), "+f"(d[1]), "+f"(d[2]), "+f"(d[3])
        : "r"(a[0]), "r"(a[1]), "r"(a[2]), "r"(a[3]), "r"(b0), "r"(b1));
}
__device__ __forceinline__ uint32_t swz(int r, int c) {
    return (uint32_t)(r * 64 + (((((c >> 4) ^ (r >> 1)) & 3) << 4) | (c & 15)));
}

// ---------------- prep ------------------------------------------------------
__global__ void k_prep(const float* __restrict__ W1, const float* __restrict__ W2,
                       const float* __restrict__ x,
                       const void* __restrict__ eraw, int E, int Nn) {
    int b = blockIdx.x, t = threadIdx.x;
    if (b == 0) {
        if (t == 0) {
            const long long* p64 = (const long long*)eraw;
            int ok64 = 1;
            int step = E / 32; if (step < 1) step = 1;
            for (int i = 0; i < 32; i++) {
                long long idx = (long long)i * step;
                if (idx >= E) break;
                long long v = p64[idx];
                if (v < 0 || v >= Nn) { ok64 = 0; break; }
            }
            g_is64 = ok64;
        }
        return;
    }
    int ZB = (Nn + 255) / 256;
    if (b - 1 < ZB) {
        int i = (b - 1) * 256 + t;
        if (i < Nn) { g_cnt[i] = 0; g_dist[i] = 0.f; }
        return;
    }
    int b2 = b - 1 - ZB;
    if (b2 < (HH * KP) / 256) {
        int idx = b2 * 256 + t;
        int n = idx >> 8, k = idx & 255;
        g_w1t[idx] = __float2half_rn(W1[k * HH + n]);
        return;
    }
    int b3 = b2 - (HH * KP) / 256;
    if (b3 < (DD * HH) / 256) {
        int idx = b3 * 256 + t;
        int n = idx >> 9, k = idx & 511;
        g_w2t[idx] = __float2half_rn(W2[k * DD + n]);
        return;
    }
    int b4 = b3 - (DD * HH) / 256;
    int idx = b4 * 256 + t;
    if (idx < Nn * DD) g_xh[idx] = __float2half_rn(x[idx]);
}

__global__ void k_edge(const void* __restrict__ eraw,
                       const float* __restrict__ ed, int E, int Nn) {
    int e = blockIdx.x * blockDim.x + threadIdx.x;
    if (e >= E) return;
    int src, dst;
    if (g_is64) {
        const long long* p = (const long long*)eraw;
        src = (int)p[e]; dst = (int)p[E + e];
    } else {
        const int* p = (const int*)eraw;
        src = p[e]; dst = p[E + e];
    }
    src = min(max(src, 0), Nn - 1);
    dst = min(max(dst, 0), Nn - 1);
    int p = atomicAdd(&g_cnt[src], 1);
    if (p < CAP) g_slots[(size_t)src * CAP + p] = dst;
    atomicAdd(&g_dist[src], ed[e]);
}

// 2 nodes per warp: 16 lanes x uint4 (16B) per row; writes agg only
__global__ void k_feat(const float* __restrict__ degrees, int Nn) {
    int warp = (blockIdx.x * blockDim.x + threadIdx.x) >> 5;
    int lane = threadIdx.x & 31;
    int sub = lane >> 4, sl = lane & 15;
    int gw = warp * 2 + sub;
    if (gw >= Nn) return;
    int cnt = g_cnt[gw]; if (cnt > CAP) cnt = CAP;
    const int* slots = g_slots + (size_t)gw * CAP;
    float acc[8];
#pragma unroll
    for (int i = 0; i < 8; i++) acc[i] = 0.f;
    int dnext = (cnt > 0) ? slots[0] : 0;
    for (int j = 0; j < cnt; j++) {
        int dcur = dnext;
        if (j + 1 < cnt) dnext = slots[j + 1];
        uint4 u = *(const uint4*)(g_xh + (size_t)dcur * DD + sl * 8);
        float2 f0 = __half22float2(*(__half2*)&u.x);
        float2 f1 = __half22float2(*(__half2*)&u.y);
        float2 f2 = __half22float2(*(__half2*)&u.z);
        float2 f3 = __half22float2(*(__half2*)&u.w);
        acc[0] += f0.x; acc[1] += f0.y; acc[2] += f1.x; acc[3] += f1.y;
        acc[4] += f2.x; acc[5] += f2.y; acc[6] += f3.x; acc[7] += f3.y;
    }
    float inv = 1.f / fmaxf(degrees[gw], 1.f);
    uint4 o;
    *(__half2*)&o.x = __floats2half2_rn(acc[0] * inv, acc[1] * inv);
    *(__half2*)&o.y = __floats2half2_rn(acc[2] * inv, acc[3] * inv);
    *(__half2*)&o.z = __floats2half2_rn(acc[4] * inv, acc[5] * inv);
    *(__half2*)&o.w = __floats2half2_rn(acc[6] * inv, acc[7] * inv);
    *(uint4*)(g_agg + (size_t)gw * DD + sl * 8) = o;
}

// ---------------------------------------------------------------------------
// GEMM common: CTA 128x128, 4 warps (2x2) of 64x64, BK=32, 3 stages of 16KB.
// ---------------------------------------------------------------------------
#define STG(s) ((s) * 16384)

struct Frag64 {
    uint32_t Ah[4][4];
    uint32_t Bh[8][2];
};
__device__ __forceinline__ void load_f(uint32_t abase, uint32_t bbase,
                                       Frag64& f) {
#pragma unroll
    for (int mf = 0; mf < 4; mf++)
        ldm_x4(abase + mf * 1024, f.Ah[mf]);
#pragma unroll
    for (int p = 0; p < 4; p++) {
        uint32_t r[4];
        ldm_x4(bbase + p * 1024, r);
        f.Bh[p * 2 + 0][0] = r[0]; f.Bh[p * 2 + 0][1] = r[2];
        f.Bh[p * 2 + 1][0] = r[1]; f.Bh[p * 2 + 1][1] = r[3];
    }
}
__device__ __forceinline__ void mma_all64(float acc[4][8][4], const Frag64& f) {
#pragma unroll
    for (int mf = 0; mf < 4; mf++)
#pragma unroll
        for (int nf = 0; nf < 8; nf++)
            mma16816(acc[mf][nf], f.Ah[mf], f.Bh[nf][0], f.Bh[nf][1]);
}

// ---------------------------------------------------------------------------
// GEMM1: h = relu([xh|agg] @ W1 + b1 + deg*W1[256] + md*W1[257]); K=256
// A loader: chunk s<4 from g_xh, s>=4 from g_agg (both 256B row stride).
// ---------------------------------------------------------------------------
#define G1_SMEM 50176
__global__ __launch_bounds__(128, 3) void k_gemm1(
    const float* __restrict__ W1, const float* __restrict__ b1,
    const float* __restrict__ degrees, int Nn) {
    extern __shared__ __align__(128) char sm[];
    uint32_t base = smem_u32(sm);
    int t = threadIdx.x, lane = t & 31, wid = t >> 5;
    int wm = wid >> 1, wn = wid & 1;
    int row0 = blockIdx.x * 128, col0 = blockIdx.y * 128;

    float* degv = (float*)(sm + 49152);
    float* mdv  = (float*)(sm + 49664);
    {
        int gr = row0 + t;
        float dr = (gr < Nn) ? degrees[gr] : 0.f;
        float ds = (gr < Nn) ? g_dist[gr] : 0.f;
        degv[t] = dr;
        mdv[t]  = ds / fmaxf(dr, 1.f);
    }

    float acc[4][8][4];
#pragma unroll
    for (int a = 0; a < 4; a++)
#pragma unroll
        for (int b = 0; b < 8; b++)
#pragma unroll
            for (int c = 0; c < 4; c++) acc[a][b][c] = 0.f;

    uint32_t aoff = swz(wm * 64 + (lane & 15), (lane >> 4) * 16);
    uint32_t boff = 8192 + swz(wn * 64 + (lane & 15), (lane >> 4) * 16);

    int lr = t >> 2, seg = (t & 3) * 16;
    const char* pX = (const char*)(g_xh + (size_t)(row0 + lr) * DD) + seg;
    const char* pG = (const char*)(g_agg + (size_t)(row0 + lr) * DD) + seg;
    const char* pB = (const char*)(g_w1t + (size_t)(col0 + lr) * KP) + seg;
    uint32_t dA = base + swz(lr, seg);
    const int RBA = DD * 2 * 32;   // 32 rows of A source = 8192 B
    const int RBB = KP * 2 * 32;   // 32 rows of B source = 16384 B

#pragma unroll 1
    for (int s = 0; s < 2; s++) {
        const char* pAs = (s < 4) ? (pX + s * 64) : (pG + (s - 4) * 64);
#pragma unroll
        for (int i = 0; i < 4; i++) {
            cp16(dA + STG(s) + 2048 * i, pAs + i * RBA);
            cp16(dA + STG(s) + 8192 + 2048 * i, pB + i * RBB + s * 64);
        }
        CP_COMMIT();
    }
#pragma unroll 1
    for (int s = 0; s < 8; s++) {
        if (s < 7) { CP_WAIT(1); } else { CP_WAIT(0); }
        __syncthreads();
        if (s + 2 < 8) {
            int s2 = s + 2, sp = s2 % 3;
            const char* pAs = (s2 < 4) ? (pX + s2 * 64) : (pG + (s2 - 4) * 64);
#pragma unroll
            for (int i = 0; i < 4; i++) {
                cp16(dA + STG(sp) + 2048 * i, pAs + i * RBA);
                cp16(dA + STG(sp) + 8192 + 2048 * i, pB + i * RBB + s2 * 64);
            }
            CP_COMMIT();
        }
        uint32_t sb = base + STG(s % 3);
#pragma unroll
        for (int ks = 0; ks < 2; ks++) {
            Frag64 f;
            load_f(sb + (aoff ^ (ks * 32u)), sb + (boff ^ (ks * 32u)), f);
            mma_all64(acc, f);
        }
    }

    // epilogue: bias + rank2 + relu -> g_h fp16
#pragma unroll
    for (int nf = 0; nf < 8; nf++) {
        int cg = col0 + wn * 64 + nf * 8 + (lane & 3) * 2;
        float b10 = __ldg(b1 + cg), b11 = __ldg(b1 + cg + 1);
        float wd0 = __ldg(W1 + 256 * HH + cg), wd1 = __ldg(W1 + 256 * HH + cg + 1);
        float wq0 = __ldg(W1 + 257 * HH + cg), wq1 = __ldg(W1 + 257 * HH + cg + 1);
#pragma unroll
        for (int mf = 0; mf < 4; mf++) {
            int rl = wm * 64 + mf * 16 + (lane >> 2);
            float d0 = degv[rl], m0 = mdv[rl];
            float d1 = degv[rl + 8], m1 = mdv[rl + 8];
            float v00 = fmaxf(acc[mf][nf][0] + b10 + d0 * wd0 + m0 * wq0, 0.f);
            float v01 = fmaxf(acc[mf][nf][1] + b11 + d0 * wd1 + m0 * wq1, 0.f);
            float v10 = fmaxf(acc[mf][nf][2] + b10 + d1 * wd0 + m1 * wq0, 0.f);
            float v11 = fmaxf(acc[mf][nf][3] + b11 + d1 * wd1 + m1 * wq1, 0.f);
            *(__half2*)(g_h + (size_t)(row0 + rl) * HH + cg) =
                __floats2half2_rn(v00, v01);
            *(__half2*)(g_h + (size_t)(row0 + rl + 8) * HH + cg) =
                __floats2half2_rn(v10, v11);
        }
    }
}

// ---------------------------------------------------------------------------
// GEMM2 + residual + LN: out = LN(x + h@W2 + b2); K=512, 16 steps
// ---------------------------------------------------------------------------
#define G2_SMEM 52224
__global__ __launch_bounds__(128, 3) void k_gemm2(
    const float* __restrict__ x, const float* __restrict__ b2,
    const float* __restrict__ gamma, const float* __restrict__ beta,
    float* __restrict__ out, int Nn) {
    extern __shared__ __align__(128) char sm[];
    uint32_t base = smem_u32(sm);
    int t = threadIdx.x, lane = t & 31, wid = t >> 5;
    int wm = wid >> 1, wn = wid & 1;
    int row0 = blockIdx.x * 128;
    float* part0 = (float*)(sm + 49152);
    float* part1 = (float*)(sm + 50176);
    float* mus   = (float*)(sm + 51200);
    float* rss   = (float*)(sm + 51712);

    float acc[4][8][4];
#pragma unroll
    for (int a = 0; a < 4; a++)
#pragma unroll
        for (int b = 0; b < 8; b++)
#pragma unroll
            for (int c = 0; c < 4; c++) acc[a][b][c] = 0.f;

    uint32_t aoff = swz(wm * 64 + (lane & 15), (lane >> 4) * 16);
    uint32_t boff = 8192 + swz(wn * 64 + (lane & 15), (lane >> 4) * 16);

    int lr = t >> 2, seg = (t & 3) * 16;
    const char* pA = (const char*)(g_h + (size_t)(row0 + lr) * HH) + seg;
    const char* pB = (const char*)(g_w2t + (size_t)lr * HH) + seg;
    uint32_t dA = base + swz(lr, seg);
    const int RB = HH * 2 * 32;

#pragma unroll 1
    for (int s = 0; s < 2; s++) {
#pragma unroll
        for (int i = 0; i < 4; i++) {
            cp16(dA + STG(s) + 2048 * i, pA + i * RB + s * 64);
            cp16(dA + STG(s) + 8192 + 2048 * i, pB + i * RB + s * 64);
        }
        CP_COMMIT();
    }
#pragma unroll 1
    for (int s = 0; s < 16; s++) {
        if (s < 15) { CP_WAIT(1); } else { CP_WAIT(0); }
        __syncthreads();
        if (s + 2 < 16) {
            int sp = (s + 2) % 3;
#pragma unroll
            for (int i = 0; i < 4; i++) {
                cp16(dA + STG(sp) + 2048 * i, pA + i * RB + (s + 2) * 64);
                cp16(dA + STG(sp) + 8192 + 2048 * i, pB + i * RB + (s + 2) * 64);
            }
            CP_COMMIT();
        }
        uint32_t sb = base + STG(s % 3);
#pragma unroll
        for (int ks = 0; ks < 2; ks++) {
            Frag64 f;
            load_f(sb + (aoff ^ (ks * 32u)), sb + (boff ^ (ks * 32u)), f);
            mma_all64(acc, f);
        }
    }

#pragma unroll
    for (int nf = 0; nf < 8; nf++) {
        int cc = wn * 64 + nf * 8 + (lane & 3) * 2;
        float b20 = __ldg(b2 + cc), b21 = __ldg(b2 + cc + 1);
#pragma unroll
        for (int mf = 0; mf < 4; mf++) {
            int g0 = row0 + wm * 64 + mf * 16 + (lane >> 2);
            float2 xv0 = make_float2(0.f, 0.f), xv1 = xv0;
            if (g0 < Nn)     xv0 = *(const float2*)(x + (size_t)g0 * DD + cc);
            if (g0 + 8 < Nn) xv1 = *(const float2*)(x + (size_t)(g0 + 8) * DD + cc);
            acc[mf][nf][0] += b20 + xv0.x;
            acc[mf][nf][1] += b21 + xv0.y;
            acc[mf][nf][2] += b20 + xv1.x;
            acc[mf][nf][3] += b21 + xv1.y;
        }
    }
#pragma unroll
    for (int mf = 0; mf < 4; mf++) {
#pragma unroll
        for (int h = 0; h < 2; h++) {
            float s0 = 0.f, s1 = 0.f;
#pragma unroll
            for (int nf = 0; nf < 8; nf++) {
                float a0 = acc[mf][nf][2 * h], a1 = acc[mf][nf][2 * h + 1];
                s0 += a0 + a1;
                s1 += a0 * a0 + a1 * a1;
            }
            s0 += __shfl_xor_sync(0xffffffffu, s0, 1);
            s1 += __shfl_xor_sync(0xffffffffu, s1, 1);
            s0 += __shfl_xor_sync(0xffffffffu, s0, 2);
            s1 += __shfl_xor_sync(0xffffffffu, s1, 2);
            if ((lane & 3) == 0) {
                int rl = wm * 64 + mf * 16 + (lane >> 2) + h * 8;
                part0[wn * 128 + rl] = s0;
                part1[wn * 128 + rl] = s1;
            }
        }
    }
    __syncthreads();
    {
        float s0 = part0[t] + part0[128 + t];
        float s1 = part1[t] + part1[128 + t];
        float mu = s0 * (1.f / 128.f);
        float var = s1 * (1.f / 128.f) - mu * mu;
        mus[t] = mu;
        rss[t] = rsqrtf(var + 1e-5f);
    }
    __syncthreads();
#pragma unroll
    for (int nf = 0; nf < 8; nf++) {
        int cc = wn * 64 + nf * 8 + (lane & 3) * 2;
        float gg0 = __ldg(gamma + cc), gg1 = __ldg(gamma + cc + 1);
        float be0 = __ldg(beta + cc), be1 = __ldg(beta + cc + 1);
#pragma unroll
        for (int mf = 0; mf < 4; mf++) {
            int rl = wm * 64 + mf * 16 + (lane >> 2);
            int g0 = row0 + rl;
            if (g0 < Nn) {
                float mu = mus[rl], rs = rss[rl];
                float2 o;
                o.x = (acc[mf][nf][0] - mu) * rs * gg0 + be0;
                o.y = (acc[mf][nf][1] - mu) * rs * gg1 + be1;
                *(float2*)(out + (size_t)g0 * DD + cc) = o;
            }
            if (g0 + 8 < Nn) {
                float mu = mus[rl + 8], rs = rss[rl + 8];
                float2 o;
                o.x = (acc[mf][nf][2] - mu) * rs * gg0 + be0;
                o.y = (acc[mf][nf][3] - mu) * rs * gg1 + be1;
                *(float2*)(out + (size_t)(g0 + 8) * DD + cc) = o;
            }
        }
    }
}

// ---------------------------------------------------------------------------
extern "C" void kernel_launch(void* const* d_in, const int* in_sizes, int n_in,
                              void* d_out, int out_size) {
    const float* x       = (const float*)d_in[0];
    const float* W1      = (const float*)d_in[1];
    const float* b1      = (const float*)d_in[2];
    const float* W2      = (const float*)d_in[3];
    const float* b2      = (const float*)d_in[4];
    const float* gamma   = (const float*)d_in[5];
    const float* beta    = (const float*)d_in[6];
    const void*  ei      = d_in[7];
    const float* ed      = (const float*)d_in[8];
    const float* degrees = (const float*)d_in[9];

    int Nn = in_sizes[0] / DD;
    int E  = in_sizes[8];

    cudaFuncSetAttribute(k_gemm1, cudaFuncAttributeMaxDynamicSharedMemorySize, G1_SMEM);
    cudaFuncSetAttribute(k_gemm2, cudaFuncAttributeMaxDynamicSharedMemorySize, G2_SMEM);

    int ZB = (Nn + 255) / 256;
    int XB = (Nn * DD + 255) / 256;
    int prep_blocks = 1 + ZB + (HH * KP) / 256 + (DD * HH) / 256 + XB;
    k_prep<<<prep_blocks, 256>>>(W1, W2, x, ei, E, Nn);
    k_edge<<<(E + 255) / 256, 256>>>(ei, ed, E, Nn);
    k_feat<<<(Nn + 15) / 16, 256>>>(degrees, Nn);

    int mt = (Nn + 127) / 128;  // 391
    k_gemm1<<<dim3(mt, 4), 128, G1_SMEM>>>(W1, b1, degrees, Nn);
    k_gemm2<<<mt, 128, G2_SMEM>>>(x, b2, gamma, beta, (float*)d_out, Nn);
}

// round 16
// speedup vs baseline: 1.1618x; 1.0706x over previous
#include <cuda_runtime.h>
#include <cuda_fp16.h>
#include <cstdint>

// ---------------------------------------------------------------------------
// ResidualGNNLayer (sm_103, fp16 mma.sync, R15 GEMM config preserved):
//   k_prep: detect + zero + TILED W1/W2 fp16 transpose + vectorized x->fp16
//   k_edge: bucket edges; k_feat: 2 nodes/warp gather-mean -> agg only
//   k_gemm1: h = relu([xh|agg]@W1 + b1 + rank2(deg,md)); A dual-source loader
//   k_gemm2: out = LN(x + h@W2 + b2)
//   GEMMs: 128 thr / 4 warps (2x2) of 64x64, BK=32, 3-stage, (128,3) bounds.
// ---------------------------------------------------------------------------

#define DD 128
#define HH 512
#define KP 256
#define CAP 128
#define NN_MAX 50048    // 391 * 128

static __device__ int   g_is64;
static __device__ int   g_cnt[NN_MAX];
static __device__ float g_dist[NN_MAX];
static __device__ int   g_slots[(size_t)NN_MAX * CAP];

static __device__ __half g_xh[(size_t)NN_MAX * DD];
static __device__ __half g_agg[(size_t)NN_MAX * DD];
static __device__ __half g_h[(size_t)NN_MAX * HH];
static __device__ __half g_w1t[HH * KP];              // [n=512][k=256]
static __device__ __half g_w2t[DD * HH];              // [n=128][k=512]

// ---------------- PTX helpers ----------------------------------------------
__device__ __forceinline__ uint32_t smem_u32(const void* p) {
    uint32_t a;
    asm("{ .reg .u64 t; cvta.to.shared.u64 t, %1; cvt.u32.u64 %0, t; }"
        : "=r"(a) : "l"(p));
    return a;
}
__device__ __forceinline__ void cp16(uint32_t d, const void* s) {
    asm volatile("cp.async.ca.shared.global [%0], [%1], 16;" :: "r"(d), "l"(s));
}
#define CP_COMMIT() asm volatile("cp.async.commit_group;" ::: "memory")
#define CP_WAIT(n)  asm volatile("cp.async.wait_group %0;" :: "n"(n) : "memory")

__device__ __forceinline__ void ldm_x4(uint32_t addr, uint32_t r[4]) {
    asm volatile("ldmatrix.sync.aligned.m8n8.x4.shared.b16 {%0,%1,%2,%3}, [%4];"
                 : "=r"(r[0]), "=r"(r[1]), "=r"(r[2]), "=r"(r[3]) : "r"(addr));
}
__device__ __forceinline__ void mma16816(float d[4], const uint32_t a[4],
                                         const uint32_t b0, const uint32_t b1) {
    asm volatile(
        "mma.sync.aligned.m16n8k16.row.col.f32.f16.f16.f32 "
        "{%0,%1,%2,%3},{%4,%5,%6,%7},{%8,%9},{%0,%1,%2,%3};"
        : "+f"(d[0]), "+f"(d[1]), "+f"(d[2]), "+f"(d[3])
        : "r"(a[0]), "r"(a[1]), "r"(a[2]), "r"(a[3]), "r"(b0), "r"(b1));
}
__device__ __forceinline__ uint32_t swz(int r, int c) {
    return (uint32_t)(r * 64 + (((((c >> 4) ^ (r >> 1)) & 3) << 4) | (c & 15)));
}

// ---------------- prep ------------------------------------------------------
// block map: [0] detect | [zero: ZB] | [W1T: 128 tiles] | [W2T: 64 tiles]
//            | [xconv: XB4 blocks of 1024 elems]
__global__ void k_prep(const float* __restrict__ W1, const float* __restrict__ W2,
                       const float* __restrict__ x,
                       const void* __restrict__ eraw, int E, int Nn) {
    __shared__ float tile[32][33];
    int b = blockIdx.x, t = threadIdx.x;
    if (b == 0) {
        if (t == 0) {
            const long long* p64 = (const long long*)eraw;
            int ok64 = 1;
            int step = E / 32; if (step < 1) step = 1;
            for (int i = 0; i < 32; i++) {
                long long idx = (long long)i * step;
                if (idx >= E) break;
                long long v = p64[idx];
                if (v < 0 || v >= Nn) { ok64 = 0; break; }
            }
            g_is64 = ok64;
        }
        return;
    }
    int ZB = (Nn + 255) / 256;
    if (b - 1 < ZB) {
        int i = (b - 1) * 256 + t;
        if (i < Nn) { g_cnt[i] = 0; g_dist[i] = 0.f; }
        return;
    }
    int b2 = b - 1 - ZB;
    int tx = t & 31, ty = t >> 5;                 // 32 x 8
    if (b2 < 128) {                               // W1T: tiles (8 k) x (16 n)
        int k0 = (b2 & 7) * 32, n0 = (b2 >> 3) * 32;
#pragma unroll
        for (int i = 0; i < 4; i++)               // coalesced read along n
            tile[ty + 8 * i][tx] = W1[(size_t)(k0 + ty + 8 * i) * HH + n0 + tx];
        __syncthreads();
#pragma unroll
        for (int i = 0; i < 4; i++)               // coalesced write along k
            g_w1t[(size_t)(n0 + ty + 8 * i) * KP + k0 + tx] =
                __float2half_rn(tile[tx][ty + 8 * i]);
        return;
    }
    int b3 = b2 - 128;
    if (b3 < 64) {                                // W2T: tiles (16 k) x (4 n)
        int k0 = (b3 & 15) * 32, n0 = (b3 >> 4) * 32;
#pragma unroll
        for (int i = 0; i < 4; i++)
            tile[ty + 8 * i][tx] = W2[(size_t)(k0 + ty + 8 * i) * DD + n0 + tx];
        __syncthreads();
#pragma unroll
        for (int i = 0; i < 4; i++)
            g_w2t[(size_t)(n0 + ty + 8 * i) * HH + k0 + tx] =
                __float2half_rn(tile[tx][ty + 8 * i]);
        return;
    }
    int b4 = b3 - 64;                             // x -> fp16, 4 elems/thread
    int idx = (b4 * 256 + t) * 4;
    if (idx < Nn * DD) {
        float4 v = *(const float4*)(x + idx);
        __half2 lo = __floats2half2_rn(v.x, v.y);
        __half2 hi = __floats2half2_rn(v.z, v.w);
        uint2 o;
        o.x = *(uint32_t*)&lo;
        o.y = *(uint32_t*)&hi;
        *(uint2*)(g_xh + idx) = o;
    }
}

__global__ void k_edge(const void* __restrict__ eraw,
                       const float* __restrict__ ed, int E, int Nn) {
    int e = blockIdx.x * blockDim.x + threadIdx.x;
    if (e >= E) return;
    int src, dst;
    if (g_is64) {
        const long long* p = (const long long*)eraw;
        src = (int)p[e]; dst = (int)p[E + e];
    } else {
        const int* p = (const int*)eraw;
        src = p[e]; dst = p[E + e];
    }
    src = min(max(src, 0), Nn - 1);
    dst = min(max(dst, 0), Nn - 1);
    int p = atomicAdd(&g_cnt[src], 1);
    if (p < CAP) g_slots[(size_t)src * CAP + p] = dst;
    atomicAdd(&g_dist[src], ed[e]);
}

// 2 nodes per warp: 16 lanes x uint4 (16B) per row; writes agg only
__global__ void k_feat(const float* __restrict__ degrees, int Nn) {
    int warp = (blockIdx.x * blockDim.x + threadIdx.x) >> 5;
    int lane = threadIdx.x & 31;
    int sub = lane >> 4, sl = lane & 15;
    int gw = warp * 2 + sub;
    if (gw >= Nn) return;
    int cnt = g_cnt[gw]; if (cnt > CAP) cnt = CAP;
    const int* slots = g_slots + (size_t)gw * CAP;
    float acc[8];
#pragma unroll
    for (int i = 0; i < 8; i++) acc[i] = 0.f;
    int dnext = (cnt > 0) ? slots[0] : 0;
    for (int j = 0; j < cnt; j++) {
        int dcur = dnext;
        if (j + 1 < cnt) dnext = slots[j + 1];
        uint4 u = *(const uint4*)(g_xh + (size_t)dcur * DD + sl * 8);
        float2 f0 = __half22float2(*(__half2*)&u.x);
        float2 f1 = __half22float2(*(__half2*)&u.y);
        float2 f2 = __half22float2(*(__half2*)&u.z);
        float2 f3 = __half22float2(*(__half2*)&u.w);
        acc[0] += f0.x; acc[1] += f0.y; acc[2] += f1.x; acc[3] += f1.y;
        acc[4] += f2.x; acc[5] += f2.y; acc[6] += f3.x; acc[7] += f3.y;
    }
    float inv = 1.f / fmaxf(degrees[gw], 1.f);
    uint4 o;
    *(__half2*)&o.x = __floats2half2_rn(acc[0] * inv, acc[1] * inv);
    *(__half2*)&o.y = __floats2half2_rn(acc[2] * inv, acc[3] * inv);
    *(__half2*)&o.z = __floats2half2_rn(acc[4] * inv, acc[5] * inv);
    *(__half2*)&o.w = __floats2half2_rn(acc[6] * inv, acc[7] * inv);
    *(uint4*)(g_agg + (size_t)gw * DD + sl * 8) = o;
}

// ---------------------------------------------------------------------------
// GEMM common: CTA 128x128, 4 warps (2x2) of 64x64, BK=32, 3 stages of 16KB.
// ---------------------------------------------------------------------------
#define STG(s) ((s) * 16384)

struct Frag64 {
    uint32_t Ah[4][4];
    uint32_t Bh[8][2];
};
__device__ __forceinline__ void load_f(uint32_t abase, uint32_t bbase,
                                       Frag64& f) {
#pragma unroll
    for (int mf = 0; mf < 4; mf++)
        ldm_x4(abase + mf * 1024, f.Ah[mf]);
#pragma unroll
    for (int p = 0; p < 4; p++) {
        uint32_t r[4];
        ldm_x4(bbase + p * 1024, r);
        f.Bh[p * 2 + 0][0] = r[0]; f.Bh[p * 2 + 0][1] = r[2];
        f.Bh[p * 2 + 1][0] = r[1]; f.Bh[p * 2 + 1][1] = r[3];
    }
}
__device__ __forceinline__ void mma_all64(float acc[4][8][4], const Frag64& f) {
#pragma unroll
    for (int mf = 0; mf < 4; mf++)
#pragma unroll
        for (int nf = 0; nf < 8; nf++)
            mma16816(acc[mf][nf], f.Ah[mf], f.Bh[nf][0], f.Bh[nf][1]);
}

// ---------------------------------------------------------------------------
// GEMM1: h = relu([xh|agg] @ W1 + b1 + deg*W1[256] + md*W1[257]); K=256
// ---------------------------------------------------------------------------
#define G1_SMEM 50176
__global__ __launch_bounds__(128, 3) void k_gemm1(
    const float* __restrict__ W1, const float* __restrict__ b1,
    const float* __restrict__ degrees, int Nn) {
    extern __shared__ __align__(128) char sm[];
    uint32_t base = smem_u32(sm);
    int t = threadIdx.x, lane = t & 31, wid = t >> 5;
    int wm = wid >> 1, wn = wid & 1;
    int row0 = blockIdx.x * 128, col0 = blockIdx.y * 128;

    float* degv = (float*)(sm + 49152);
    float* mdv  = (float*)(sm + 49664);
    {
        int gr = row0 + t;
        float dr = (gr < Nn) ? degrees[gr] : 0.f;
        float ds = (gr < Nn) ? g_dist[gr] : 0.f;
        degv[t] = dr;
        mdv[t]  = ds / fmaxf(dr, 1.f);
    }

    float acc[4][8][4];
#pragma unroll
    for (int a = 0; a < 4; a++)
#pragma unroll
        for (int b = 0; b < 8; b++)
#pragma unroll
            for (int c = 0; c < 4; c++) acc[a][b][c] = 0.f;

    uint32_t aoff = swz(wm * 64 + (lane & 15), (lane >> 4) * 16);
    uint32_t boff = 8192 + swz(wn * 64 + (lane & 15), (lane >> 4) * 16);

    int lr = t >> 2, seg = (t & 3) * 16;
    const char* pX = (const char*)(g_xh + (size_t)(row0 + lr) * DD) + seg;
    const char* pG = (const char*)(g_agg + (size_t)(row0 + lr) * DD) + seg;
    const char* pB = (const char*)(g_w1t + (size_t)(col0 + lr) * KP) + seg;
    uint32_t dA = base + swz(lr, seg);
    const int RBA = DD * 2 * 32;   // 32 rows of A source = 8192 B
    const int RBB = KP * 2 * 32;   // 32 rows of B source = 16384 B

#pragma unroll 1
    for (int s = 0; s < 2; s++) {
        const char* pAs = (s < 4) ? (pX + s * 64) : (pG + (s - 4) * 64);
#pragma unroll
        for (int i = 0; i < 4; i++) {
            cp16(dA + STG(s) + 2048 * i, pAs + i * RBA);
            cp16(dA + STG(s) + 8192 + 2048 * i, pB + i * RBB + s * 64);
        }
        CP_COMMIT();
    }
#pragma unroll 1
    for (int s = 0; s < 8; s++) {
        if (s < 7) { CP_WAIT(1); } else { CP_WAIT(0); }
        __syncthreads();
        if (s + 2 < 8) {
            int s2 = s + 2, sp = s2 % 3;
            const char* pAs = (s2 < 4) ? (pX + s2 * 64) : (pG + (s2 - 4) * 64);
#pragma unroll
            for (int i = 0; i < 4; i++) {
                cp16(dA + STG(sp) + 2048 * i, pAs + i * RBA);
                cp16(dA + STG(sp) + 8192 + 2048 * i, pB + i * RBB + s2 * 64);
            }
            CP_COMMIT();
        }
        uint32_t sb = base + STG(s % 3);
#pragma unroll
        for (int ks = 0; ks < 2; ks++) {
            Frag64 f;
            load_f(sb + (aoff ^ (ks * 32u)), sb + (boff ^ (ks * 32u)), f);
            mma_all64(acc, f);
        }
    }

    // epilogue: bias + rank2 + relu -> g_h fp16
#pragma unroll
    for (int nf = 0; nf < 8; nf++) {
        int cg = col0 + wn * 64 + nf * 8 + (lane & 3) * 2;
        float b10 = __ldg(b1 + cg), b11 = __ldg(b1 + cg + 1);
        float wd0 = __ldg(W1 + 256 * HH + cg), wd1 = __ldg(W1 + 256 * HH + cg + 1);
        float wq0 = __ldg(W1 + 257 * HH + cg), wq1 = __ldg(W1 + 257 * HH + cg + 1);
#pragma unroll
        for (int mf = 0; mf < 4; mf++) {
            int rl = wm * 64 + mf * 16 + (lane >> 2);
            float d0 = degv[rl], m0 = mdv[rl];
            float d1 = degv[rl + 8], m1 = mdv[rl + 8];
            float v00 = fmaxf(acc[mf][nf][0] + b10 + d0 * wd0 + m0 * wq0, 0.f);
            float v01 = fmaxf(acc[mf][nf][1] + b11 + d0 * wd1 + m0 * wq1, 0.f);
            float v10 = fmaxf(acc[mf][nf][2] + b10 + d1 * wd0 + m1 * wq0, 0.f);
            float v11 = fmaxf(acc[mf][nf][3] + b11 + d1 * wd1 + m1 * wq1, 0.f);
            *(__half2*)(g_h + (size_t)(row0 + rl) * HH + cg) =
                __floats2half2_rn(v00, v01);
            *(__half2*)(g_h + (size_t)(row0 + rl + 8) * HH + cg) =
                __floats2half2_rn(v10, v11);
        }
    }
}

// ---------------------------------------------------------------------------
// GEMM2 + residual + LN: out = LN(x + h@W2 + b2); K=512, 16 steps
// ---------------------------------------------------------------------------
#define G2_SMEM 52224
__global__ __launch_bounds__(128, 3) void k_gemm2(
    const float* __restrict__ x, const float* __restrict__ b2,
    const float* __restrict__ gamma, const float* __restrict__ beta,
    float* __restrict__ out, int Nn) {
    extern __shared__ __align__(128) char sm[];
    uint32_t base = smem_u32(sm);
    int t = threadIdx.x, lane = t & 31, wid = t >> 5;
    int wm = wid >> 1, wn = wid & 1;
    int row0 = blockIdx.x * 128;
    float* part0 = (float*)(sm + 49152);
    float* part1 = (float*)(sm + 50176);
    float* mus   = (float*)(sm + 51200);
    float* rss   = (float*)(sm + 51712);

    float acc[4][8][4];
#pragma unroll
    for (int a = 0; a < 4; a++)
#pragma unroll
        for (int b = 0; b < 8; b++)
#pragma unroll
            for (int c = 0; c < 4; c++) acc[a][b][c] = 0.f;

    uint32_t aoff = swz(wm * 64 + (lane & 15), (lane >> 4) * 16);
    uint32_t boff = 8192 + swz(wn * 64 + (lane & 15), (lane >> 4) * 16);

    int lr = t >> 2, seg = (t & 3) * 16;
    const char* pA = (const char*)(g_h + (size_t)(row0 + lr) * HH) + seg;
    const char* pB = (const char*)(g_w2t + (size_t)lr * HH) + seg;
    uint32_t dA = base + swz(lr, seg);
    const int RB = HH * 2 * 32;

#pragma unroll 1
    for (int s = 0; s < 2; s++) {
#pragma unroll
        for (int i = 0; i < 4; i++) {
            cp16(dA + STG(s) + 2048 * i, pA + i * RB + s * 64);
            cp16(dA + STG(s) + 8192 + 2048 * i, pB + i * RB + s * 64);
        }
        CP_COMMIT();
    }
#pragma unroll 1
    for (int s = 0; s < 16; s++) {
        if (s < 15) { CP_WAIT(1); } else { CP_WAIT(0); }
        __syncthreads();
        if (s + 2 < 16) {
            int sp = (s + 2) % 3;
#pragma unroll
            for (int i = 0; i < 4; i++) {
                cp16(dA + STG(sp) + 2048 * i, pA + i * RB + (s + 2) * 64);
                cp16(dA + STG(sp) + 8192 + 2048 * i, pB + i * RB + (s + 2) * 64);
            }
            CP_COMMIT();
        }
        uint32_t sb = base + STG(s % 3);
#pragma unroll
        for (int ks = 0; ks < 2; ks++) {
            Frag64 f;
            load_f(sb + (aoff ^ (ks * 32u)), sb + (boff ^ (ks * 32u)), f);
            mma_all64(acc, f);
        }
    }

#pragma unroll
    for (int nf = 0; nf < 8; nf++) {
        int cc = wn * 64 + nf * 8 + (lane & 3) * 2;
        float b20 = __ldg(b2 + cc), b21 = __ldg(b2 + cc + 1);
#pragma unroll
        for (int mf = 0; mf < 4; mf++) {
            int g0 = row0 + wm * 64 + mf * 16 + (lane >> 2);
            float2 xv0 = make_float2(0.f, 0.f), xv1 = xv0;
            if (g0 < Nn)     xv0 = *(const float2*)(x + (size_t)g0 * DD + cc);
            if (g0 + 8 < Nn) xv1 = *(const float2*)(x + (size_t)(g0 + 8) * DD + cc);
            acc[mf][nf][0] += b20 + xv0.x;
            acc[mf][nf][1] += b21 + xv0.y;
            acc[mf][nf][2] += b20 + xv1.x;
            acc[mf][nf][3] += b21 + xv1.y;
        }
    }
#pragma unroll
    for (int mf = 0; mf < 4; mf++) {
#pragma unroll
        for (int h = 0; h < 2; h++) {
            float s0 = 0.f, s1 = 0.f;
#pragma unroll
            for (int nf = 0; nf < 8; nf++) {
                float a0 = acc[mf][nf][2 * h], a1 = acc[mf][nf][2 * h + 1];
                s0 += a0 + a1;
                s1 += a0 * a0 + a1 * a1;
            }
            s0 += __shfl_xor_sync(0xffffffffu, s0, 1);
            s1 += __shfl_xor_sync(0xffffffffu, s1, 1);
            s0 += __shfl_xor_sync(0xffffffffu, s0, 2);
            s1 += __shfl_xor_sync(0xffffffffu, s1, 2);
            if ((lane & 3) == 0) {
                int rl = wm * 64 + mf * 16 + (lane >> 2) + h * 8;
                part0[wn * 128 + rl] = s0;
                part1[wn * 128 + rl] = s1;
            }
        }
    }
    __syncthreads();
    {
        float s0 = part0[t] + part0[128 + t];
        float s1 = part1[t] + part1[128 + t];
        float mu = s0 * (1.f / 128.f);
        float var = s1 * (1.f / 128.f) - mu * mu;
        mus[t] = mu;
        rss[t] = rsqrtf(var + 1e-5f);
    }
    __syncthreads();
#pragma unroll
    for (int nf = 0; nf < 8; nf++) {
        int cc = wn * 64 + nf * 8 + (lane & 3) * 2;
        float gg0 = __ldg(gamma + cc), gg1 = __ldg(gamma + cc + 1);
        float be0 = __ldg(beta + cc), be1 = __ldg(beta + cc + 1);
#pragma unroll
        for (int mf = 0; mf < 4; mf++) {
            int rl = wm * 64 + mf * 16 + (lane >> 2);
            int g0 = row0 + rl;
            if (g0 < Nn) {
                float mu = mus[rl], rs = rss[rl];
                float2 o;
                o.x = (acc[mf][nf][0] - mu) * rs * gg0 + be0;
                o.y = (acc[mf][nf][1] - mu) * rs * gg1 + be1;
                *(float2*)(out + (size_t)g0 * DD + cc) = o;
            }
            if (g0 + 8 < Nn) {
                float mu = mus[rl + 8], rs = rss[rl + 8];
                float2 o;
                o.x = (acc[mf][nf][2] - mu) * rs * gg0 + be0;
                o.y = (acc[mf][nf][3] - mu) * rs * gg1 + be1;
                *(float2*)(out + (size_t)(g0 + 8) * DD + cc) = o;
            }
        }
    }
}

// ---------------------------------------------------------------------------
extern "C" void kernel_launch(void* const* d_in, const int* in_sizes, int n_in,
                              void* d_out, int out_size) {
    const float* x       = (const float*)d_in[0];
    const float* W1      = (const float*)d_in[1];
    const float* b1      = (const float*)d_in[2];
    const float* W2      = (const float*)d_in[3];
    const float* b2      = (const float*)d_in[4];
    const float* gamma   = (const float*)d_in[5];
    const float* beta    = (const float*)d_in[6];
    const void*  ei      = d_in[7];
    const float* ed      = (const float*)d_in[8];
    const float* degrees = (const float*)d_in[9];

    int Nn = in_sizes[0] / DD;
    int E  = in_sizes[8];

    cudaFuncSetAttribute(k_gemm1, cudaFuncAttributeMaxDynamicSharedMemorySize, G1_SMEM);
    cudaFuncSetAttribute(k_gemm2, cudaFuncAttributeMaxDynamicSharedMemorySize, G2_SMEM);

    int ZB = (Nn + 255) / 256;
    int XB4 = (Nn * DD + 1023) / 1024;
    int prep_blocks = 1 + ZB + 128 + 64 + XB4;
    k_prep<<<prep_blocks, 256>>>(W1, W2, x, ei, E, Nn);
    k_edge<<<(E + 255) / 256, 256>>>(ei, ed, E, Nn);
    k_feat<<<(Nn + 15) / 16, 256>>>(degrees, Nn);

    int mt = (Nn + 127) / 128;  // 391
    k_gemm1<<<dim3(mt, 4), 128, G1_SMEM>>>(W1, b1, degrees, Nn);
    k_gemm2<<<mt, 128, G2_SMEM>>>(x, b2, gamma, beta, (float*)d_out, Nn);
}

// round 17
// speedup vs baseline: 1.1675x; 1.0050x over previous
#include <cuda_runtime.h>
#include <cuda_fp16.h>
#include <cstdint>

// ---------------------------------------------------------------------------
// ResidualGNNLayer (sm_103, fp16 mma.sync):
//   k_init: detect idx dtype + zero counters
//   k_main: edge bucketing + tiled W1/W2 fp16 transpose + x->fp16 (one launch,
//           independent block ranges overlap atomic-, L2-, DRAM-bound work)
//   k_feat: 2 nodes/warp gather-mean (2-way unrolled) -> agg
//   k_gemm1 / k_gemm2: unchanged R15/R16 champion config
// ---------------------------------------------------------------------------

#define DD 128
#define HH 512
#define KP 256
#define CAP 128
#define NN_MAX 50048    // 391 * 128

static __device__ int   g_is64;
static __device__ int   g_cnt[NN_MAX];
static __device__ float g_dist[NN_MAX];
static __device__ int   g_slots[(size_t)NN_MAX * CAP];

static __device__ __half g_xh[(size_t)NN_MAX * DD];
static __device__ __half g_agg[(size_t)NN_MAX * DD];
static __device__ __half g_h[(size_t)NN_MAX * HH];
static __device__ __half g_w1t[HH * KP];              // [n=512][k=256]
static __device__ __half g_w2t[DD * HH];              // [n=128][k=512]

// ---------------- PTX helpers ----------------------------------------------
__device__ __forceinline__ uint32_t smem_u32(const void* p) {
    uint32_t a;
    asm("{ .reg .u64 t; cvta.to.shared.u64 t, %1; cvt.u32.u64 %0, t; }"
        : "=r"(a) : "l"(p));
    return a;
}
__device__ __forceinline__ void cp16(uint32_t d, const void* s) {
    asm volatile("cp.async.ca.shared.global [%0], [%1], 16;" :: "r"(d), "l"(s));
}
#define CP_COMMIT() asm volatile("cp.async.commit_group;" ::: "memory")
#define CP_WAIT(n)  asm volatile("cp.async.wait_group %0;" :: "n"(n) : "memory")

__device__ __forceinline__ void ldm_x4(uint32_t addr, uint32_t r[4]) {
    asm volatile("ldmatrix.sync.aligned.m8n8.x4.shared.b16 {%0,%1,%2,%3}, [%4];"
                 : "=r"(r[0]), "=r"(r[1]), "=r"(r[2]), "=r"(r[3]) : "r"(addr));
}
__device__ __forceinline__ void mma16816(float d[4], const uint32_t a[4],
                                         const uint32_t b0, const uint32_t b1) {
    asm volatile(
        "mma.sync.aligned.m16n8k16.row.col.f32.f16.f16.f32 "
        "{%0,%1,%2,%3},{%4,%5,%6,%7},{%8,%9},{%0,%1,%2,%3};"
        : "+f"(d[0]), "+f"(d[1]), "+f"(d[2]), "+f"(d[3])
        : "r"(a[0]), "r"(a[1]), "r"(a[2]), "r"(a[3]), "r"(b0), "r"(b1));
}
__device__ __forceinline__ uint32_t swz(int r, int c) {
    return (uint32_t)(r * 64 + (((((c >> 4) ^ (r >> 1)) & 3) << 4) | (c & 15)));
}

// ---------------- init: detect + zero ----------------------------------------
__global__ void k_init(const void* __restrict__ eraw, int E, int Nn) {
    int b = blockIdx.x, t = threadIdx.x;
    if (b == 0 && t == 0) {
        const long long* p64 = (const long long*)eraw;
        int ok64 = 1;
        int step = E / 32; if (step < 1) step = 1;
        for (int i = 0; i < 32; i++) {
            long long idx = (long long)i * step;
            if (idx >= E) break;
            long long v = p64[idx];
            if (v < 0 || v >= Nn) { ok64 = 0; break; }
        }
        g_is64 = ok64;
    }
    int i = b * 256 + t;
    if (i < Nn) { g_cnt[i] = 0; g_dist[i] = 0.f; }
}

// ---------------- main prep: edge + W transposes + x->fp16 (overlapped) ------
// block map: [0, EB) edge | [EB, EB+128) W1T | +64 W2T | + XB4 xconv
__global__ void k_main(const void* __restrict__ eraw, const float* __restrict__ ed,
                       const float* __restrict__ W1, const float* __restrict__ W2,
                       const float* __restrict__ x, int E, int Nn, int EB) {
    __shared__ float tile[32][33];
    int b = blockIdx.x, t = threadIdx.x;
    if (b < EB) {                                  // ---- edge bucketing ----
        int e = b * 256 + t;
        if (e >= E) return;
        int src, dst;
        if (g_is64) {
            const long long* p = (const long long*)eraw;
            src = (int)p[e]; dst = (int)p[E + e];
        } else {
            const int* p = (const int*)eraw;
            src = p[e]; dst = p[E + e];
        }
        src = min(max(src, 0), Nn - 1);
        dst = min(max(dst, 0), Nn - 1);
        int p = atomicAdd(&g_cnt[src], 1);
        if (p < CAP) g_slots[(size_t)src * CAP + p] = dst;
        atomicAdd(&g_dist[src], ed[e]);
        return;
    }
    int b2 = b - EB;
    int tx = t & 31, ty = t >> 5;                  // 32 x 8
    if (b2 < 128) {                                // ---- W1T tiles ----
        int k0 = (b2 & 7) * 32, n0 = (b2 >> 3) * 32;
#pragma unroll
        for (int i = 0; i < 4; i++)
            tile[ty + 8 * i][tx] = W1[(size_t)(k0 + ty + 8 * i) * HH + n0 + tx];
        __syncthreads();
#pragma unroll
        for (int i = 0; i < 4; i++)
            g_w1t[(size_t)(n0 + ty + 8 * i) * KP + k0 + tx] =
                __float2half_rn(tile[tx][ty + 8 * i]);
        return;
    }
    int b3 = b2 - 128;
    if (b3 < 64) {                                 // ---- W2T tiles ----
        int k0 = (b3 & 15) * 32, n0 = (b3 >> 4) * 32;
#pragma unroll
        for (int i = 0; i < 4; i++)
            tile[ty + 8 * i][tx] = W2[(size_t)(k0 + ty + 8 * i) * DD + n0 + tx];
        __syncthreads();
#pragma unroll
        for (int i = 0; i < 4; i++)
            g_w2t[(size_t)(n0 + ty + 8 * i) * HH + k0 + tx] =
                __float2half_rn(tile[tx][ty + 8 * i]);
        return;
    }
    int b4 = b3 - 64;                              // ---- x -> fp16 ----
    int idx = (b4 * 256 + t) * 4;
    if (idx < Nn * DD) {
        float4 v = *(const float4*)(x + idx);
        __half2 lo = __floats2half2_rn(v.x, v.y);
        __half2 hi = __floats2half2_rn(v.z, v.w);
        uint2 o;
        o.x = *(uint32_t*)&lo;
        o.y = *(uint32_t*)&hi;
        *(uint2*)(g_xh + idx) = o;
    }
}

// 2 nodes per warp; neighbor loop 2-way unrolled for MLP
__global__ void k_feat(const float* __restrict__ degrees, int Nn) {
    int warp = (blockIdx.x * blockDim.x + threadIdx.x) >> 5;
    int lane = threadIdx.x & 31;
    int sub = lane >> 4, sl = lane & 15;
    int gw = warp * 2 + sub;
    if (gw >= Nn) return;
    int cnt = g_cnt[gw]; if (cnt > CAP) cnt = CAP;
    const int* slots = g_slots + (size_t)gw * CAP;
    float acc[8];
#pragma unroll
    for (int i = 0; i < 8; i++) acc[i] = 0.f;
    int j = 0;
    for (; j + 2 <= cnt; j += 2) {
        int d0 = slots[j], d1 = slots[j + 1];
        uint4 u0 = *(const uint4*)(g_xh + (size_t)d0 * DD + sl * 8);
        uint4 u1 = *(const uint4*)(g_xh + (size_t)d1 * DD + sl * 8);
        float2 a0 = __half22float2(*(__half2*)&u0.x);
        float2 a1 = __half22float2(*(__half2*)&u0.y);
        float2 a2 = __half22float2(*(__half2*)&u0.z);
        float2 a3 = __half22float2(*(__half2*)&u0.w);
        float2 c0 = __half22float2(*(__half2*)&u1.x);
        float2 c1 = __half22float2(*(__half2*)&u1.y);
        float2 c2 = __half22float2(*(__half2*)&u1.z);
        float2 c3 = __half22float2(*(__half2*)&u1.w);
        acc[0] += a0.x + c0.x; acc[1] += a0.y + c0.y;
        acc[2] += a1.x + c1.x; acc[3] += a1.y + c1.y;
        acc[4] += a2.x + c2.x; acc[5] += a2.y + c2.y;
        acc[6] += a3.x + c3.x; acc[7] += a3.y + c3.y;
    }
    if (j < cnt) {
        int d0 = slots[j];
        uint4 u0 = *(const uint4*)(g_xh + (size_t)d0 * DD + sl * 8);
        float2 a0 = __half22float2(*(__half2*)&u0.x);
        float2 a1 = __half22float2(*(__half2*)&u0.y);
        float2 a2 = __half22float2(*(__half2*)&u0.z);
        float2 a3 = __half22float2(*(__half2*)&u0.w);
        acc[0] += a0.x; acc[1] += a0.y; acc[2] += a1.x; acc[3] += a1.y;
        acc[4] += a2.x; acc[5] += a2.y; acc[6] += a3.x; acc[7] += a3.y;
    }
    float inv = 1.f / fmaxf(degrees[gw], 1.f);
    uint4 o;
    *(__half2*)&o.x = __floats2half2_rn(acc[0] * inv, acc[1] * inv);
    *(__half2*)&o.y = __floats2half2_rn(acc[2] * inv, acc[3] * inv);
    *(__half2*)&o.z = __floats2half2_rn(acc[4] * inv, acc[5] * inv);
    *(__half2*)&o.w = __floats2half2_rn(acc[6] * inv, acc[7] * inv);
    *(uint4*)(g_agg + (size_t)gw * DD + sl * 8) = o;
}

// ---------------------------------------------------------------------------
// GEMM common: CTA 128x128, 4 warps (2x2) of 64x64, BK=32, 3 stages of 16KB.
// ---------------------------------------------------------------------------
#define STG(s) ((s) * 16384)

struct Frag64 {
    uint32_t Ah[4][4];
    uint32_t Bh[8][2];
};
__device__ __forceinline__ void load_f(uint32_t abase, uint32_t bbase,
                                       Frag64& f) {
#pragma unroll
    for (int mf = 0; mf < 4; mf++)
        ldm_x4(abase + mf * 1024, f.Ah[mf]);
#pragma unroll
    for (int p = 0; p < 4; p++) {
        uint32_t r[4];
        ldm_x4(bbase + p * 1024, r);
        f.Bh[p * 2 + 0][0] = r[0]; f.Bh[p * 2 + 0][1] = r[2];
        f.Bh[p * 2 + 1][0] = r[1]; f.Bh[p * 2 + 1][1] = r[3];
    }
}
__device__ __forceinline__ void mma_all64(float acc[4][8][4], const Frag64& f) {
#pragma unroll
    for (int mf = 0; mf < 4; mf++)
#pragma unroll
        for (int nf = 0; nf < 8; nf++)
            mma16816(acc[mf][nf], f.Ah[mf], f.Bh[nf][0], f.Bh[nf][1]);
}

// ---------------------------------------------------------------------------
// GEMM1: h = relu([xh|agg] @ W1 + b1 + deg*W1[256] + md*W1[257]); K=256
// ---------------------------------------------------------------------------
#define G1_SMEM 50176
__global__ __launch_bounds__(128, 3) void k_gemm1(
    const float* __restrict__ W1, const float* __restrict__ b1,
    const float* __restrict__ degrees, int Nn) {
    extern __shared__ __align__(128) char sm[];
    uint32_t base = smem_u32(sm);
    int t = threadIdx.x, lane = t & 31, wid = t >> 5;
    int wm = wid >> 1, wn = wid & 1;
    int row0 = blockIdx.x * 128, col0 = blockIdx.y * 128;

    float* degv = (float*)(sm + 49152);
    float* mdv  = (float*)(sm + 49664);
    {
        int gr = row0 + t;
        float dr = (gr < Nn) ? degrees[gr] : 0.f;
        float ds = (gr < Nn) ? g_dist[gr] : 0.f;
        degv[t] = dr;
        mdv[t]  = ds / fmaxf(dr, 1.f);
    }

    float acc[4][8][4];
#pragma unroll
    for (int a = 0; a < 4; a++)
#pragma unroll
        for (int b = 0; b < 8; b++)
#pragma unroll
            for (int c = 0; c < 4; c++) acc[a][b][c] = 0.f;

    uint32_t aoff = swz(wm * 64 + (lane & 15), (lane >> 4) * 16);
    uint32_t boff = 8192 + swz(wn * 64 + (lane & 15), (lane >> 4) * 16);

    int lr = t >> 2, seg = (t & 3) * 16;
    const char* pX = (const char*)(g_xh + (size_t)(row0 + lr) * DD) + seg;
    const char* pG = (const char*)(g_agg + (size_t)(row0 + lr) * DD) + seg;
    const char* pB = (const char*)(g_w1t + (size_t)(col0 + lr) * KP) + seg;
    uint32_t dA = base + swz(lr, seg);
    const int RBA = DD * 2 * 32;   // 8192 B
    const int RBB = KP * 2 * 32;   // 16384 B

#pragma unroll 1
    for (int s = 0; s < 2; s++) {
        const char* pAs = (s < 4) ? (pX + s * 64) : (pG + (s - 4) * 64);
#pragma unroll
        for (int i = 0; i < 4; i++) {
            cp16(dA + STG(s) + 2048 * i, pAs + i * RBA);
            cp16(dA + STG(s) + 8192 + 2048 * i, pB + i * RBB + s * 64);
        }
        CP_COMMIT();
    }
#pragma unroll 1
    for (int s = 0; s < 8; s++) {
        if (s < 7) { CP_WAIT(1); } else { CP_WAIT(0); }
        __syncthreads();
        if (s + 2 < 8) {
            int s2 = s + 2, sp = s2 % 3;
            const char* pAs = (s2 < 4) ? (pX + s2 * 64) : (pG + (s2 - 4) * 64);
#pragma unroll
            for (int i = 0; i < 4; i++) {
                cp16(dA + STG(sp) + 2048 * i, pAs + i * RBA);
                cp16(dA + STG(sp) + 8192 + 2048 * i, pB + i * RBB + s2 * 64);
            }
            CP_COMMIT();
        }
        uint32_t sb = base + STG(s % 3);
#pragma unroll
        for (int ks = 0; ks < 2; ks++) {
            Frag64 f;
            load_f(sb + (aoff ^ (ks * 32u)), sb + (boff ^ (ks * 32u)), f);
            mma_all64(acc, f);
        }
    }

    // epilogue: bias + rank2 + relu -> g_h fp16
#pragma unroll
    for (int nf = 0; nf < 8; nf++) {
        int cg = col0 + wn * 64 + nf * 8 + (lane & 3) * 2;
        float b10 = __ldg(b1 + cg), b11 = __ldg(b1 + cg + 1);
        float wd0 = __ldg(W1 + 256 * HH + cg), wd1 = __ldg(W1 + 256 * HH + cg + 1);
        float wq0 = __ldg(W1 + 257 * HH + cg), wq1 = __ldg(W1 + 257 * HH + cg + 1);
#pragma unroll
        for (int mf = 0; mf < 4; mf++) {
            int rl = wm * 64 + mf * 16 + (lane >> 2);
            float d0 = degv[rl], m0 = mdv[rl];
            float d1 = degv[rl + 8], m1 = mdv[rl + 8];
            float v00 = fmaxf(acc[mf][nf][0] + b10 + d0 * wd0 + m0 * wq0, 0.f);
            float v01 = fmaxf(acc[mf][nf][1] + b11 + d0 * wd1 + m0 * wq1, 0.f);
            float v10 = fmaxf(acc[mf][nf][2] + b10 + d1 * wd0 + m1 * wq0, 0.f);
            float v11 = fmaxf(acc[mf][nf][3] + b11 + d1 * wd1 + m1 * wq1, 0.f);
            *(__half2*)(g_h + (size_t)(row0 + rl) * HH + cg) =
                __floats2half2_rn(v00, v01);
            *(__half2*)(g_h + (size_t)(row0 + rl + 8) * HH + cg) =
                __floats2half2_rn(v10, v11);
        }
    }
}

// ---------------------------------------------------------------------------
// GEMM2 + residual + LN: out = LN(x + h@W2 + b2); K=512, 16 steps
// ---------------------------------------------------------------------------
#define G2_SMEM 52224
__global__ __launch_bounds__(128, 3) void k_gemm2(
    const float* __restrict__ x, const float* __restrict__ b2,
    const float* __restrict__ gamma, const float* __restrict__ beta,
    float* __restrict__ out, int Nn) {
    extern __shared__ __align__(128) char sm[];
    uint32_t base = smem_u32(sm);
    int t = threadIdx.x, lane = t & 31, wid = t >> 5;
    int wm = wid >> 1, wn = wid & 1;
    int row0 = blockIdx.x * 128;
    float* part0 = (float*)(sm + 49152);
    float* part1 = (float*)(sm + 50176);
    float* mus   = (float*)(sm + 51200);
    float* rss   = (float*)(sm + 51712);

    float acc[4][8][4];
#pragma unroll
    for (int a = 0; a < 4; a++)
#pragma unroll
        for (int b = 0; b < 8; b++)
#pragma unroll
            for (int c = 0; c < 4; c++) acc[a][b][c] = 0.f;

    uint32_t aoff = swz(wm * 64 + (lane & 15), (lane >> 4) * 16);
    uint32_t boff = 8192 + swz(wn * 64 + (lane & 15), (lane >> 4) * 16);

    int lr = t >> 2, seg = (t & 3) * 16;
    const char* pA = (const char*)(g_h + (size_t)(row0 + lr) * HH) + seg;
    const char* pB = (const char*)(g_w2t + (size_t)lr * HH) + seg;
    uint32_t dA = base + swz(lr, seg);
    const int RB = HH * 2 * 32;

#pragma unroll 1
    for (int s = 0; s < 2; s++) {
#pragma unroll
        for (int i = 0; i < 4; i++) {
            cp16(dA + STG(s) + 2048 * i, pA + i * RB + s * 64);
            cp16(dA + STG(s) + 8192 + 2048 * i, pB + i * RB + s * 64);
        }
        CP_COMMIT();
    }
#pragma unroll 1
    for (int s = 0; s < 16; s++) {
        if (s < 15) { CP_WAIT(1); } else { CP_WAIT(0); }
        __syncthreads();
        if (s + 2 < 16) {
            int sp = (s + 2) % 3;
#pragma unroll
            for (int i = 0; i < 4; i++) {
                cp16(dA + STG(sp) + 2048 * i, pA + i * RB + (s + 2) * 64);
                cp16(dA + STG(sp) + 8192 + 2048 * i, pB + i * RB + (s + 2) * 64);
            }
            CP_COMMIT();
        }
        uint32_t sb = base + STG(s % 3);
#pragma unroll
        for (int ks = 0; ks < 2; ks++) {
            Frag64 f;
            load_f(sb + (aoff ^ (ks * 32u)), sb + (boff ^ (ks * 32u)), f);
            mma_all64(acc, f);
        }
    }

#pragma unroll
    for (int nf = 0; nf < 8; nf++) {
        int cc = wn * 64 + nf * 8 + (lane & 3) * 2;
        float b20 = __ldg(b2 + cc), b21 = __ldg(b2 + cc + 1);
#pragma unroll
        for (int mf = 0; mf < 4; mf++) {
            int g0 = row0 + wm * 64 + mf * 16 + (lane >> 2);
            float2 xv0 = make_float2(0.f, 0.f), xv1 = xv0;
            if (g0 < Nn)     xv0 = *(const float2*)(x + (size_t)g0 * DD + cc);
            if (g0 + 8 < Nn) xv1 = *(const float2*)(x + (size_t)(g0 + 8) * DD + cc);
            acc[mf][nf][0] += b20 + xv0.x;
            acc[mf][nf][1] += b21 + xv0.y;
            acc[mf][nf][2] += b20 + xv1.x;
            acc[mf][nf][3] += b21 + xv1.y;
        }
    }
#pragma unroll
    for (int mf = 0; mf < 4; mf++) {
#pragma unroll
        for (int h = 0; h < 2; h++) {
            float s0 = 0.f, s1 = 0.f;
#pragma unroll
            for (int nf = 0; nf < 8; nf++) {
                float a0 = acc[mf][nf][2 * h], a1 = acc[mf][nf][2 * h + 1];
                s0 += a0 + a1;
                s1 += a0 * a0 + a1 * a1;
            }
            s0 += __shfl_xor_sync(0xffffffffu, s0, 1);
            s1 += __shfl_xor_sync(0xffffffffu, s1, 1);
            s0 += __shfl_xor_sync(0xffffffffu, s0, 2);
            s1 += __shfl_xor_sync(0xffffffffu, s1, 2);
            if ((lane & 3) == 0) {
                int rl = wm * 64 + mf * 16 + (lane >> 2) + h * 8;
                part0[wn * 128 + rl] = s0;
                part1[wn * 128 + rl] = s1;
            }
        }
    }
    __syncthreads();
    {
        float s0 = part0[t] + part0[128 + t];
        float s1 = part1[t] + part1[128 + t];
        float mu = s0 * (1.f / 128.f);
        float var = s1 * (1.f / 128.f) - mu * mu;
        mus[t] = mu;
        rss[t] = rsqrtf(var + 1e-5f);
    }
    __syncthreads();
#pragma unroll
    for (int nf = 0; nf < 8; nf++) {
        int cc = wn * 64 + nf * 8 + (lane & 3) * 2;
        float gg0 = __ldg(gamma + cc), gg1 = __ldg(gamma + cc + 1);
        float be0 = __ldg(beta + cc), be1 = __ldg(beta + cc + 1);
#pragma unroll
        for (int mf = 0; mf < 4; mf++) {
            int rl = wm * 64 + mf * 16 + (lane >> 2);
            int g0 = row0 + rl;
            if (g0 < Nn) {
                float mu = mus[rl], rs = rss[rl];
                float2 o;
                o.x = (acc[mf][nf][0] - mu) * rs * gg0 + be0;
                o.y = (acc[mf][nf][1] - mu) * rs * gg1 + be1;
                *(float2*)(out + (size_t)g0 * DD + cc) = o;
            }
            if (g0 + 8 < Nn) {
                float mu = mus[rl + 8], rs = rss[rl + 8];
                float2 o;
                o.x = (acc[mf][nf][2] - mu) * rs * gg0 + be0;
                o.y = (acc[mf][nf][3] - mu) * rs * gg1 + be1;
                *(float2*)(out + (size_t)(g0 + 8) * DD + cc) = o;
            }
        }
    }
}

// ---------------------------------------------------------------------------
extern "C" void kernel_launch(void* const* d_in, const int* in_sizes, int n_in,
                              void* d_out, int out_size) {
    const float* x       = (const float*)d_in[0];
    const float* W1      = (const float*)d_in[1];
    const float* b1      = (const float*)d_in[2];
    const float* W2      = (const float*)d_in[3];
    const float* b2      = (const float*)d_in[4];
    const float* gamma   = (const float*)d_in[5];
    const float* beta    = (const float*)d_in[6];
    const void*  ei      = d_in[7];
    const float* ed      = (const float*)d_in[8];
    const float* degrees = (const float*)d_in[9];

    int Nn = in_sizes[0] / DD;
    int E  = in_sizes[8];

    cudaFuncSetAttribute(k_gemm1, cudaFuncAttributeMaxDynamicSharedMemorySize, G1_SMEM);
    cudaFuncSetAttribute(k_gemm2, cudaFuncAttributeMaxDynamicSharedMemorySize, G2_SMEM);

    int ZB = (Nn + 255) / 256;
    int EB = (E + 255) / 256;
    int XB4 = (Nn * DD + 1023) / 1024;
    k_init<<<ZB, 256>>>(ei, E, Nn);
    k_main<<<EB + 128 + 64 + XB4, 256>>>(ei, ed, W1, W2, x, E, Nn, EB);
    k_feat<<<(Nn + 15) / 16, 256>>>(degrees, Nn);

    int mt = (Nn + 127) / 128;  // 391
    k_gemm1<<<dim3(mt, 4), 128, G1_SMEM>>>(W1, b1, degrees, Nn);
    k_gemm2<<<mt, 128, G2_SMEM>>>(x, b2, gamma, beta, (float*)d_out, Nn);
}